// round 14
// baseline (speedup 1.0000x reference)
#include <cuda_runtime.h>
#include <cuda_fp16.h>
#include <cstdint>

#define N_NODES 50000
#define N_EDGES 600000
#define LN_EPS 1e-5f

// ---------------- device-global scratch (no allocations allowed) ------------
__device__ float g_agg[N_NODES * 128];
__device__ __half g_nf[N_NODES * 128];
__device__ __half g_ag[N_NODES * 128];
// Weights per K-64 subchunk, PRE-SWIZZLED (ldmatrix XOR layout), 16KB each.
// Edge: sc 0-5 = We1 (K=384), 6-7 = We2. Node: sc 0-3 = Wn1, 4-5 = Wn2.
__device__ __align__(16) __half g_We[8 * 8192];
__device__ __align__(16) __half g_Wn[6 * 8192];

// ---------------- smem layout (bytes) ---------------------------------------
// X buf: 64 rows x 128B, SINGLE buffer (prefetch lives in regs). H uses
// XB(0)+XB(1) after GEMM1. W: two 16KB bufs (bulk-DMA filled).
#define XB(i)     ((uint32_t)(i) * 8192u)
#define WB(i)     (16384u + (uint32_t)(i) * 16384u)
#define BIAS1_OFF 49152
#define BIAS2_OFF 49664
#define GAM_OFF   50176
#define BET_OFF   50688
#define SIDX_OFF  51200
#define RIDX_OFF  51456
#define PART_OFF  51712
#define MBAR_OFF  53760          // 2 x 8B mbarriers for W bulk copies
#define SMEM_TOTAL 53824

// ---------------- helpers ----------------------------------------------------
__device__ __forceinline__ uint32_t smem_u32(const void* p) {
    uint32_t a;
    asm("{ .reg .u64 t; cvta.to.shared.u64 t, %1; cvt.u32.u64 %0, t; }"
        : "=r"(a) : "l"(p));
    return a;
}
__device__ __forceinline__ void ldsm4(uint32_t (&r)[4], uint32_t a) {
    asm volatile("ldmatrix.sync.aligned.m8n8.x4.shared.b16 {%0,%1,%2,%3}, [%4];"
                 : "=r"(r[0]), "=r"(r[1]), "=r"(r[2]), "=r"(r[3]) : "r"(a));
}
__device__ __forceinline__ void mma16816(float (&d)[4], const uint32_t (&a)[4],
                                         uint32_t b0, uint32_t b1) {
    asm volatile(
        "mma.sync.aligned.m16n8k16.row.col.f32.f16.f16.f32 "
        "{%0,%1,%2,%3}, {%4,%5,%6,%7}, {%8,%9}, {%0,%1,%2,%3};"
        : "+f"(d[0]), "+f"(d[1]), "+f"(d[2]), "+f"(d[3])
        : "r"(a[0]), "r"(a[1]), "r"(a[2]), "r"(a[3]), "r"(b0), "r"(b1));
}
__device__ __forceinline__ void red_add_v2(float* p, float a, float b) {
    asm volatile("red.global.add.v2.f32 [%0], {%1, %2};"
                 :: "l"(p), "f"(a), "f"(b) : "memory");
}
__device__ __forceinline__ void mbar_init(uint32_t a, uint32_t c) {
    asm volatile("mbarrier.init.shared.b64 [%0], %1;" :: "r"(a), "r"(c) : "memory");
}
__device__ __forceinline__ void mbar_expect(uint32_t a, uint32_t bytes) {
    asm volatile("mbarrier.arrive.expect_tx.shared.b64 _, [%0], %1;"
                 :: "r"(a), "r"(bytes) : "memory");
}
__device__ __forceinline__ void bulk_g2s(uint32_t dst, const void* src,
                                         uint32_t bytes, uint32_t mbar) {
    asm volatile(
        "cp.async.bulk.shared::cta.global.mbarrier::complete_tx::bytes "
        "[%0], [%1], %2, [%3];"
        :: "r"(dst), "l"(src), "r"(bytes), "r"(mbar) : "memory");
}
__device__ __forceinline__ void mbar_wait(uint32_t addr, uint32_t parity) {
    uint32_t done;
    do {
        asm volatile(
            "{\n\t.reg .pred P;\n\t"
            "mbarrier.try_wait.parity.acquire.cta.shared::cta.b64 P, [%1], %2, 0x989680;\n\t"
            "selp.b32 %0, 1, 0, P;\n\t}"
            : "=r"(done) : "r"(addr), "r"(parity) : "memory");
    } while (!done);
}

// pack two fp32 -> fp16x2
__device__ __forceinline__ uint32_t pack2h(float a, float b) {
    __half2 h = __floats2half2_rn(a, b);
    return *(uint32_t*)&h;
}

// ---------------- utility kernels (device symbols referenced in DEVICE code) -
__global__ void zero_agg_kernel() {
    int i = blockIdx.x * blockDim.x + threadIdx.x;
    ((float4*)g_agg)[i] = make_float4(0.f, 0.f, 0.f, 0.f);
}
__global__ void conv_nf_kernel(const float* __restrict__ src) {
    int i = blockIdx.x * blockDim.x + threadIdx.x;   // N_NODES*32 float4s
    float4 v = ((const float4*)src)[i];
    ((uint2*)g_nf)[i] = make_uint2(pack2h(v.x, v.y), pack2h(v.z, v.w));
}
__global__ void conv_agg_kernel() {
    int i = blockIdx.x * blockDim.x + threadIdx.x;
    float4 v = ((const float4*)g_agg)[i];
    ((uint2*)g_ag)[i] = make_uint2(pack2h(v.x, v.y), pack2h(v.z, v.w));
}
// Write W pre-swizzled: element (n, kk) -> byte n*128 + ((kk>>3 ^ (n&7))<<4) + (kk&7)*2
__global__ void prep_w(const float* __restrict__ We1, const float* __restrict__ We2,
                       const float* __restrict__ Wn1, const float* __restrict__ Wn2) {
    int idx = blockIdx.x * blockDim.x + threadIdx.x;
    if (idx >= 114688) return;
    char* dst;
    float v;
    int n, kk;
    if (idx < 65536) {
        int sc = idx >> 13, rem = idx & 8191;
        n = rem >> 6; kk = rem & 63;
        v = (sc < 6) ? We1[(sc * 64 + kk) * 128 + n] : We2[((sc - 6) * 64 + kk) * 128 + n];
        dst = (char*)(g_We + sc * 8192);
    } else {
        int j = idx - 65536;
        int sc = j >> 13, rem = j & 8191;
        n = rem >> 6; kk = rem & 63;
        v = (sc < 4) ? Wn1[(sc * 64 + kk) * 128 + n] : Wn2[((sc - 4) * 64 + kk) * 128 + n];
        dst = (char*)(g_Wn + sc * 8192);
    }
    uint32_t off = (uint32_t)n * 128 + (uint32_t)(((kk >> 3) ^ (n & 7)) << 4) +
                   (uint32_t)(kk & 7) * 2;
    *(__half*)(dst + off) = __float2half_rn(v);
}

// ---------------- main fused tile kernel -------------------------------------
// 256 threads, 3 CTAs/SM, 2x4 warp grid (warp tile 32x32), M tile 64.
// 1-pass fp16 GEMM. W via cp.async.bulk (pre-swizzled global). X via LDG.128
// register prefetch (one subchunk ahead) + STS.128 (single smem buffer).
template <int S1, bool EDGE>
__global__ void __launch_bounds__(256, 3)
gnb_kernel(const float* __restrict__ nf, const float* __restrict__ ef,
           const int* __restrict__ snd, const int* __restrict__ rcv,
           const float* __restrict__ b1, const float* __restrict__ b2,
           const float* __restrict__ gam, const float* __restrict__ bet,
           float* __restrict__ out) {
    extern __shared__ char smem[];
    const uint32_t sb = smem_u32(smem);
    const int tid = threadIdx.x, lane = tid & 31, wid = tid >> 5;
    const int wrow = wid >> 2, wcol = wid & 3;
    const int base = blockIdx.x * 64;
    const int total = EDGE ? N_EDGES : N_NODES;
    const int valid = min(64, total - base);

    if (tid == 0) {
        mbar_init(sb + MBAR_OFF, 1);
        mbar_init(sb + MBAR_OFF + 8, 1);
    }
    if (tid < 128) {
        ((float*)(smem + BIAS1_OFF))[tid] = b1[tid];
        ((float*)(smem + BIAS2_OFF))[tid] = b2[tid];
        ((float*)(smem + GAM_OFF))[tid] = gam[tid];
        ((float*)(smem + BET_OFF))[tid] = bet[tid];
    }
    if (EDGE && tid < 64) {
        ((int*)(smem + SIDX_OFF))[tid] = (tid < valid) ? snd[base + tid] : 0;
        ((int*)(smem + RIDX_OFF))[tid] = (tid < valid) ? rcv[base + tid] : 0;
    }
    __syncthreads();

    // per-lane ldsm constants (swizzled: block b at row r lives at (b ^ (r&7))*16)
    const int aHi = lane >> 4;
    const int rA = wrow * 32 + (lane & 15);
    const int xA = rA & 7;
    const uint32_t aRow = (uint32_t)rA * 128;
    const int bHi = (lane >> 3) & 1;
    const int rB = wcol * 32 + (lane & 7) + ((lane >> 4) << 3);
    const int xB = rB & 7;
    const uint32_t bRow = (uint32_t)rB * 128;
    const int g = lane >> 2, t4 = lane & 3;

    // bulk W load: one DMA per 16KB subchunk (pre-swizzled in global)
    auto issueW = [&](int sc, int buf) {
        if (tid == 0) {
            const __half* gW = EDGE ? g_We : g_Wn;
            mbar_expect(sb + MBAR_OFF + 8 * buf, 16384u);
            bulk_g2s(sb + WB(buf), gW + sc * 8192, 16384u, sb + MBAR_OFF + 8 * buf);
        }
    };

    // X register prefetch: 4 threads/row, 32 B (16 halves) each -> 8 uint32
    uint32_t xreg[8];
    const int xrow = tid >> 2, xq = tid & 3;
    auto ldgX = [&](int s) {
        const int cs = s >> 1, kh = s & 1;
        const bool ok = xrow < valid;
        if (EDGE && cs == 2) {
            // ef fp32 -> cvt to fp16 on arrival
            const float* src = ef + (size_t)(base + xrow) * 128 + kh * 64 + xq * 16;
#pragma unroll
            for (int j = 0; j < 4; ++j) {
                float4 v = ok ? ((const float4*)src)[j]
                              : make_float4(0.f, 0.f, 0.f, 0.f);
                xreg[j * 2]     = pack2h(v.x, v.y);
                xreg[j * 2 + 1] = pack2h(v.z, v.w);
            }
        } else {
            int gr;
            const __half* sH;
            if (EDGE) {
                gr = ((const int*)(smem + (cs == 0 ? SIDX_OFF : RIDX_OFF)))[xrow];
                sH = g_nf;
            } else {
                gr = base + xrow;
                if (gr >= total) gr = total - 1;
                sH = (cs == 0) ? g_nf : g_ag;
            }
            const __half* src = sH + (size_t)gr * 128 + kh * 64 + xq * 16;
            uint4 a = ((const uint4*)src)[0];
            uint4 b = ((const uint4*)src)[1];
            if (!ok) { a = make_uint4(0,0,0,0); b = make_uint4(0,0,0,0); }
            xreg[0] = a.x; xreg[1] = a.y; xreg[2] = a.z; xreg[3] = a.w;
            xreg[4] = b.x; xreg[5] = b.y; xreg[6] = b.z; xreg[7] = b.w;
        }
    };
    auto stsX = [&]() {
        char* tb = smem;                          // XB(0)
#pragma unroll
        for (int j = 0; j < 2; ++j) {
            const int kk = xq * 16 + j * 8;
            const int blk = kk >> 3;
            const uint32_t o = (uint32_t)xrow * 128 +
                               (uint32_t)((blk ^ (xrow & 7)) << 4);
            *(uint4*)(tb + o) = make_uint4(xreg[j * 4], xreg[j * 4 + 1],
                                           xreg[j * 4 + 2], xreg[j * 4 + 3]);
        }
    };
    // 64-wide-K subchunk: acc += X*W, 1-pass fp16.
    auto compute_sub = [&](float (&acc)[2][4][4], uint32_t xbase, uint32_t wbase) {
#pragma unroll
        for (int ks = 0; ks < 4; ++ks) {
            const uint32_t oA = aRow + (uint32_t)((((2 * ks + aHi) ^ xA)) << 4);
            const uint32_t oB = bRow + (uint32_t)((((2 * ks + bHi) ^ xB)) << 4);
            uint32_t ah[2][4], bh[2][4];
            ldsm4(ah[0], xbase + oA);
            ldsm4(ah[1], xbase + oA + 2048);
            ldsm4(bh[0], wbase + oB);
            ldsm4(bh[1], wbase + oB + 2048);
#pragma unroll
            for (int mi = 0; mi < 2; ++mi)
#pragma unroll
                for (int nj = 0; nj < 2; ++nj) {
                    mma16816(acc[mi][2 * nj],     ah[mi], bh[nj][0], bh[nj][1]);
                    mma16816(acc[mi][2 * nj + 1], ah[mi], bh[nj][2], bh[nj][3]);
                }
        }
    };

    float acc[2][4][4];
#pragma unroll
    for (int mi = 0; mi < 2; ++mi)
#pragma unroll
        for (int ni = 0; ni < 4; ++ni)
#pragma unroll
            for (int r = 0; r < 4; ++r) acc[mi][ni][r] = 0.f;

    // ---------------- GEMM1: pipelined over S1 subchunks --------------------
    ldgX(0);
    issueW(0, 0);
#pragma unroll
    for (int s = 0; s < S1; ++s) {
        mbar_wait(sb + MBAR_OFF + 8 * (s & 1), (s >> 1) & 1);   // W buf ready
        __syncthreads();            // prev compute done -> X buf writable
        stsX();                     // write X(s) from regs
        __syncthreads();            // X visible
        if (s + 1 < S1) {
            ldgX(s + 1);            // prefetch next X into regs
            issueW(s + 1, (s + 1) & 1);
        }
        compute_sub(acc, sb, sb + WB(s & 1));
    }
    __syncthreads();                // all GEMM1 reads done

    // ---------------- W2 prefetch (safe: all GEMM1 compute done) ------------
    issueW(S1, 0);
    issueW(S1 + 1, 1);

    // ---------------- epilogue 1: h = relu(y1+b1) -> H tiles ----------------
    {
        const float* s_b1 = (const float*)(smem + BIAS1_OFF);
#pragma unroll
        for (int mi = 0; mi < 2; ++mi) {
            const int r0 = wrow * 32 + mi * 16 + g, r1 = r0 + 8;
#pragma unroll
            for (int ni = 0; ni < 4; ++ni) {
                const int col = wcol * 32 + ni * 8 + t4 * 2;
                const float ba = s_b1[col], bb = s_b1[col + 1];
                float v0 = fmaxf(acc[mi][ni][0] + ba, 0.f);
                float v1 = fmaxf(acc[mi][ni][1] + bb, 0.f);
                float v2 = fmaxf(acc[mi][ni][2] + ba, 0.f);
                float v3 = fmaxf(acc[mi][ni][3] + bb, 0.f);
                uint32_t h0 = pack2h(v0, v1);
                uint32_t h1 = pack2h(v2, v3);
                const int sub = col >> 6, kk = col & 63;
                const int bblk = kk >> 3, w2 = (kk & 7) * 2;
                char* tb = smem + sub * 8192;     // H subchunk -> XB(sub)
                char* d0 = tb + r0 * 128 + (((bblk ^ (r0 & 7))) << 4) + w2;
                char* d1 = tb + r1 * 128 + (((bblk ^ (r1 & 7))) << 4) + w2;
                *(uint32_t*)d0 = h0;
                *(uint32_t*)d1 = h1;
            }
        }
        // reset accumulators for GEMM2 (register reuse)
#pragma unroll
        for (int mi = 0; mi < 2; ++mi)
#pragma unroll
            for (int ni = 0; ni < 4; ++ni)
#pragma unroll
                for (int r = 0; r < 4; ++r) acc[mi][ni][r] = 0.f;
    }
    mbar_wait(sb + MBAR_OFF, (S1 / 2) & 1);
    mbar_wait(sb + MBAR_OFF + 8, (S1 / 2) & 1);
    __syncthreads();

    // ---------------- GEMM2: 2 subchunks (H in XB0/XB1, W2 in WB0/WB1) ------
    compute_sub(acc, sb + XB(0), sb + WB(0));
    compute_sub(acc, sb + XB(1), sb + WB(1));

    // ---------------- epilogue 2: LayerNorm + residual + scatter ------------
    {
        const float* s_b2 = (const float*)(smem + BIAS2_OFF);
        float s[2][2] = {{0.f, 0.f}, {0.f, 0.f}};
        float ss[2][2] = {{0.f, 0.f}, {0.f, 0.f}};
#pragma unroll
        for (int mi = 0; mi < 2; ++mi)
#pragma unroll
            for (int ni = 0; ni < 4; ++ni) {
                const int col = wcol * 32 + ni * 8 + t4 * 2;
                const float ba = s_b2[col], bb = s_b2[col + 1];
                float y0 = acc[mi][ni][0] + ba, y1 = acc[mi][ni][1] + bb;
                float y2 = acc[mi][ni][2] + ba, y3 = acc[mi][ni][3] + bb;
                acc[mi][ni][0] = y0; acc[mi][ni][1] = y1;
                acc[mi][ni][2] = y2; acc[mi][ni][3] = y3;
                s[mi][0] += y0 + y1; ss[mi][0] += y0 * y0 + y1 * y1;
                s[mi][1] += y2 + y3; ss[mi][1] += y2 * y2 + y3 * y3;
            }
#pragma unroll
        for (int off = 1; off <= 2; off <<= 1)
#pragma unroll
            for (int mi = 0; mi < 2; ++mi)
#pragma unroll
                for (int h = 0; h < 2; ++h) {
                    s[mi][h] += __shfl_xor_sync(0xffffffffu, s[mi][h], off);
                    ss[mi][h] += __shfl_xor_sync(0xffffffffu, ss[mi][h], off);
                }
        float2* part = (float2*)(smem + PART_OFF);
        if (t4 == 0)
#pragma unroll
            for (int mi = 0; mi < 2; ++mi)
#pragma unroll
                for (int h = 0; h < 2; ++h) {
                    const int row = wrow * 32 + mi * 16 + g + h * 8;
                    part[row * 4 + wcol] = make_float2(s[mi][h], ss[mi][h]);
                }
        __syncthreads();

        const float* s_g = (const float*)(smem + GAM_OFF);
        const float* s_bb = (const float*)(smem + BET_OFF);
#pragma unroll
        for (int mi = 0; mi < 2; ++mi)
#pragma unroll
            for (int h = 0; h < 2; ++h) {
                const int row = wrow * 32 + mi * 16 + g + h * 8;
                if (row >= valid) continue;
                float2 p0 = part[row * 4], p1 = part[row * 4 + 1];
                float2 p2 = part[row * 4 + 2], p3 = part[row * 4 + 3];
                const float mu = (p0.x + p1.x + p2.x + p3.x) * (1.f / 128.f);
                const float var =
                    (p0.y + p1.y + p2.y + p3.y) * (1.f / 128.f) - mu * mu;
                const float inv = rsqrtf(var + LN_EPS);
                const size_t gro = (size_t)(base + row) * 128;
                const float* res = (EDGE ? ef : nf) + gro;
                float* op = out + gro;
                float* ap = nullptr;
                if (EDGE) {
                    const int rv = ((const int*)(smem + RIDX_OFF))[row];
                    ap = g_agg + (size_t)rv * 128;
                }
#pragma unroll
                for (int ni = 0; ni < 4; ++ni) {
                    const int col = wcol * 32 + ni * 8 + t4 * 2;
                    const float y0 = acc[mi][ni][h * 2];
                    const float y1 = acc[mi][ni][h * 2 + 1];
                    const float m0 = (y0 - mu) * inv * s_g[col] + s_bb[col];
                    const float m1 = (y1 - mu) * inv * s_g[col + 1] + s_bb[col + 1];
                    if (EDGE) red_add_v2(ap + col, m0, m1);
                    float2 r2 = *(const float2*)(res + col);
                    *(float2*)(op + col) = make_float2(m0 + r2.x, m1 + r2.y);
                }
            }
    }
}

// ---------------------------------------------------------------------------
extern "C" void kernel_launch(void* const* d_in, const int* in_sizes, int n_in,
                              void* d_out, int out_size) {
    const float* nf  = (const float*)d_in[0];
    const float* ef  = (const float*)d_in[1];
    const int*   snd = (const int*)d_in[2];
    const int*   rcv = (const int*)d_in[3];
    const float* We1 = (const float*)d_in[4];
    const float* be1 = (const float*)d_in[5];
    const float* We2 = (const float*)d_in[6];
    const float* be2 = (const float*)d_in[7];
    const float* ge  = (const float*)d_in[8];
    const float* bbe = (const float*)d_in[9];
    const float* Wn1 = (const float*)d_in[10];
    const float* bn1 = (const float*)d_in[11];
    const float* Wn2 = (const float*)d_in[12];
    const float* bn2 = (const float*)d_in[13];
    const float* gn  = (const float*)d_in[14];
    const float* bbn = (const float*)d_in[15];

    float* out_nodes = (float*)d_out;
    float* out_edges = out_nodes + (size_t)N_NODES * 128;

    cudaFuncSetAttribute(gnb_kernel<6, true>,
                         cudaFuncAttributeMaxDynamicSharedMemorySize, SMEM_TOTAL);
    cudaFuncSetAttribute(gnb_kernel<4, false>,
                         cudaFuncAttributeMaxDynamicSharedMemorySize, SMEM_TOTAL);

    prep_w<<<448, 256>>>(We1, We2, Wn1, Wn2);
    conv_nf_kernel<<<6250, 256>>>(nf);       // 50000*32 float4s
    zero_agg_kernel<<<6250, 256>>>();

    gnb_kernel<6, true><<<N_EDGES / 64, 256, SMEM_TOTAL>>>(
        nf, ef, snd, rcv, be1, be2, ge, bbe, out_edges);

    conv_agg_kernel<<<6250, 256>>>();

    gnb_kernel<4, false><<<(N_NODES + 63) / 64, 256, SMEM_TOTAL>>>(
        nf, nullptr, nullptr, nullptr, bn1, bn2, gn, bbn, out_nodes);
}

// round 15
// speedup vs baseline: 1.5755x; 1.5755x over previous
#include <cuda_runtime.h>
#include <cuda_fp16.h>
#include <cstdint>

#define N_NODES 50000
#define N_EDGES 600000
#define LN_EPS 1e-5f

// ---------------- device-global scratch (no allocations allowed) ------------
__device__ float g_agg[N_NODES * 128];
__device__ __half g_nf[N_NODES * 128];
__device__ __half g_ag[N_NODES * 128];
// Weights per K-64 subchunk, PRE-SWIZZLED (ldmatrix XOR layout), 16KB each.
// Edge: sc 0-5 = We1 (K=384), 6-7 = We2. Node: sc 0-3 = Wn1, 4-5 = Wn2.
__device__ __align__(16) __half g_We[8 * 8192];
__device__ __align__(16) __half g_Wn[6 * 8192];

// ---------------- smem layout (bytes) ---------------------------------------
// X sub-tile buf: 64 rows x 128B (fp16). Two bufs (cp.async double-buffered).
// W sub-tile buf: 128 rows x 128B (fp16). Two bufs (bulk-DMA filled).
#define XB(i)     ((uint32_t)(i) * 8192u)
#define WB(i)     (16384u + (uint32_t)(i) * 16384u)
#define BIAS1_OFF 49152
#define BIAS2_OFF 49664
#define GAM_OFF   50176
#define BET_OFF   50688
#define SIDX_OFF  51200
#define RIDX_OFF  51456
#define PART_OFF  51712
#define MBAR_OFF  53760          // 2 x 8B mbarriers for W bulk copies
#define SMEM_TOTAL 53824

// ---------------- helpers ----------------------------------------------------
__device__ __forceinline__ uint32_t smem_u32(const void* p) {
    uint32_t a;
    asm("{ .reg .u64 t; cvta.to.shared.u64 t, %1; cvt.u32.u64 %0, t; }"
        : "=r"(a) : "l"(p));
    return a;
}
__device__ __forceinline__ void ldsm4(uint32_t (&r)[4], uint32_t a) {
    asm volatile("ldmatrix.sync.aligned.m8n8.x4.shared.b16 {%0,%1,%2,%3}, [%4];"
                 : "=r"(r[0]), "=r"(r[1]), "=r"(r[2]), "=r"(r[3]) : "r"(a));
}
__device__ __forceinline__ void mma16816(float (&d)[4], const uint32_t (&a)[4],
                                         uint32_t b0, uint32_t b1) {
    asm volatile(
        "mma.sync.aligned.m16n8k16.row.col.f32.f16.f16.f32 "
        "{%0,%1,%2,%3}, {%4,%5,%6,%7}, {%8,%9}, {%0,%1,%2,%3};"
        : "+f"(d[0]), "+f"(d[1]), "+f"(d[2]), "+f"(d[3])
        : "r"(a[0]), "r"(a[1]), "r"(a[2]), "r"(a[3]), "r"(b0), "r"(b1));
}
__device__ __forceinline__ void red_add_v2(float* p, float a, float b) {
    asm volatile("red.global.add.v2.f32 [%0], {%1, %2};"
                 :: "l"(p), "f"(a), "f"(b) : "memory");
}
__device__ __forceinline__ void cp_async16z(uint32_t d, const void* s, uint32_t sz) {
    asm volatile("cp.async.cg.shared.global [%0], [%1], 16, %2;"
                 :: "r"(d), "l"(s), "r"(sz) : "memory");
}
#define CP_COMMIT() asm volatile("cp.async.commit_group;" ::: "memory")
#define CP_WAIT0()  asm volatile("cp.async.wait_group 0;" ::: "memory")

__device__ __forceinline__ void mbar_init(uint32_t a, uint32_t c) {
    asm volatile("mbarrier.init.shared.b64 [%0], %1;" :: "r"(a), "r"(c) : "memory");
}
__device__ __forceinline__ void mbar_expect(uint32_t a, uint32_t bytes) {
    asm volatile("mbarrier.arrive.expect_tx.shared.b64 _, [%0], %1;"
                 :: "r"(a), "r"(bytes) : "memory");
}
__device__ __forceinline__ void bulk_g2s(uint32_t dst, const void* src,
                                         uint32_t bytes, uint32_t mbar) {
    asm volatile(
        "cp.async.bulk.shared::cta.global.mbarrier::complete_tx::bytes "
        "[%0], [%1], %2, [%3];"
        :: "r"(dst), "l"(src), "r"(bytes), "r"(mbar) : "memory");
}
__device__ __forceinline__ void mbar_wait(uint32_t addr, uint32_t parity) {
    uint32_t done;
    do {
        asm volatile(
            "{\n\t.reg .pred P;\n\t"
            "mbarrier.try_wait.parity.acquire.cta.shared::cta.b64 P, [%1], %2, 0x989680;\n\t"
            "selp.b32 %0, 1, 0, P;\n\t}"
            : "=r"(done) : "r"(addr), "r"(parity) : "memory");
    } while (!done);
}

// pack two fp32 -> fp16x2
__device__ __forceinline__ uint32_t pack2h(float a, float b) {
    __half2 h = __floats2half2_rn(a, b);
    return *(uint32_t*)&h;
}

// ---------------- utility kernels (device symbols referenced in DEVICE code) -
__global__ void zero_agg_kernel() {
    int i = blockIdx.x * blockDim.x + threadIdx.x;
    ((float4*)g_agg)[i] = make_float4(0.f, 0.f, 0.f, 0.f);
}
__global__ void conv_nf_kernel(const float* __restrict__ src) {
    int i = blockIdx.x * blockDim.x + threadIdx.x;   // N_NODES*32 float4s
    float4 v = ((const float4*)src)[i];
    ((uint2*)g_nf)[i] = make_uint2(pack2h(v.x, v.y), pack2h(v.z, v.w));
}
__global__ void conv_agg_kernel() {
    int i = blockIdx.x * blockDim.x + threadIdx.x;
    float4 v = ((const float4*)g_agg)[i];
    ((uint2*)g_ag)[i] = make_uint2(pack2h(v.x, v.y), pack2h(v.z, v.w));
}
// Write W pre-swizzled: element (n, kk) -> byte n*128 + ((kk>>3 ^ (n&7))<<4) + (kk&7)*2
__global__ void prep_w(const float* __restrict__ We1, const float* __restrict__ We2,
                       const float* __restrict__ Wn1, const float* __restrict__ Wn2) {
    int idx = blockIdx.x * blockDim.x + threadIdx.x;
    if (idx >= 114688) return;
    char* dst;
    float v;
    int n, kk;
    if (idx < 65536) {
        int sc = idx >> 13, rem = idx & 8191;
        n = rem >> 6; kk = rem & 63;
        v = (sc < 6) ? We1[(sc * 64 + kk) * 128 + n] : We2[((sc - 6) * 64 + kk) * 128 + n];
        dst = (char*)(g_We + sc * 8192);
    } else {
        int j = idx - 65536;
        int sc = j >> 13, rem = j & 8191;
        n = rem >> 6; kk = rem & 63;
        v = (sc < 4) ? Wn1[(sc * 64 + kk) * 128 + n] : Wn2[((sc - 4) * 64 + kk) * 128 + n];
        dst = (char*)(g_Wn + sc * 8192);
    }
    uint32_t off = (uint32_t)n * 128 + (uint32_t)(((kk >> 3) ^ (n & 7)) << 4) +
                   (uint32_t)(kk & 7) * 2;
    *(__half*)(dst + off) = __float2half_rn(v);
}

// ---------------- main fused tile kernel -------------------------------------
// 128 threads, 4 CTAs/SM, 2x2 warp grid (warp tile 32x64), M tile 64.
// 1-pass fp16 GEMM. W via cp.async.bulk (pre-swizzled global). X via cp.async
// double-buffer; EDGE converts ef inline (LDG prefetch + cvt + STS.128).
template <int S1, bool EDGE>
__global__ void __launch_bounds__(128, 4)
gnb_kernel(const float* __restrict__ nf, const float* __restrict__ ef,
           const int* __restrict__ snd, const int* __restrict__ rcv,
           const float* __restrict__ b1, const float* __restrict__ b2,
           const float* __restrict__ gam, const float* __restrict__ bet,
           float* __restrict__ out) {
    extern __shared__ char smem[];
    const uint32_t sb = smem_u32(smem);
    const int tid = threadIdx.x, lane = tid & 31, wid = tid >> 5;
    const int wrow = wid >> 1, wcol = wid & 1;       // 2 x 2 warp grid
    const int base = blockIdx.x * 64;
    const int total = EDGE ? N_EDGES : N_NODES;
    const int valid = min(64, total - base);

    if (tid == 0) {
        mbar_init(sb + MBAR_OFF, 1);
        mbar_init(sb + MBAR_OFF + 8, 1);
    }
    {
        ((float*)(smem + BIAS1_OFF))[tid] = b1[tid];
        ((float*)(smem + BIAS2_OFF))[tid] = b2[tid];
        ((float*)(smem + GAM_OFF))[tid] = gam[tid];
        ((float*)(smem + BET_OFF))[tid] = bet[tid];
    }
    if (EDGE && tid < 64) {
        ((int*)(smem + SIDX_OFF))[tid] = (tid < valid) ? snd[base + tid] : 0;
        ((int*)(smem + RIDX_OFF))[tid] = (tid < valid) ? rcv[base + tid] : 0;
    }
    __syncthreads();

    // per-lane ldsm constants (swizzled: block b at row r lives at (b ^ (r&7))*16)
    const int aHi = lane >> 4;
    const int rA = wrow * 32 + (lane & 15);
    const int xA = rA & 7;
    const uint32_t aRow = (uint32_t)rA * 128;
    const int bHi = (lane >> 3) & 1;
    const int rB = wcol * 64 + (lane & 7) + ((lane >> 4) << 3);
    const int xB = rB & 7;
    const uint32_t bRow = (uint32_t)rB * 128;
    const int g = lane >> 2, t4 = lane & 3;

    // bulk W load: one DMA per 16KB subchunk (pre-swizzled in global)
    auto issueW = [&](int sc, int buf) {
        if (tid == 0) {
            const __half* gW = EDGE ? g_We : g_Wn;
            mbar_expect(sb + MBAR_OFF + 8 * buf, 16384u);
            bulk_g2s(sb + WB(buf), gW + sc * 8192, 16384u, sb + MBAR_OFF + 8 * buf);
        }
    };
    auto issueX = [&](int s, uint32_t xoff) {
        const int cs = s >> 1, kh = s & 1;
#pragma unroll
        for (int p = 0; p < 4; ++p) {
            int m = p * 128 + tid;                  // 512 16B chunks
            int row = m >> 3, b = m & 7;
            int gr;
            const __half* sH;
            if (EDGE) {
                gr = ((const int*)(smem + (cs == 0 ? SIDX_OFF : RIDX_OFF)))[row];
                sH = g_nf;
            } else {
                gr = base + row;
                if (gr >= total) gr = total - 1;
                sH = (cs == 0) ? g_nf : g_ag;
            }
            const __half* src = sH + (size_t)gr * 128 + kh * 64 + b * 8;
            uint32_t dst = sb + xoff + (uint32_t)row * 128 +
                           (uint32_t)((b ^ (row & 7)) << 4);
            cp_async16z(dst, src, (row < valid) ? 16u : 0u);
        }
    };
    // ef fp32 prefetch (coalesced stream, one subchunk ahead), cvt on arrival
    uint32_t efreg[16];
    const int efrow = tid >> 1, efq = tid & 1;      // 2 threads/row, 32 cols
    auto ldgEF = [&](int s) {
        const int kh = s & 1;
        const float* src = ef + (size_t)(base + efrow) * 128 + kh * 64 + efq * 32;
#pragma unroll
        for (int j = 0; j < 8; ++j) {
            float4 v = ((const float4*)src)[j];
            efreg[j * 2]     = pack2h(v.x, v.y);
            efreg[j * 2 + 1] = pack2h(v.z, v.w);
        }
    };
    auto stsEF = [&](uint32_t xoff) {
        char* tb = smem + xoff;
#pragma unroll
        for (int j = 0; j < 4; ++j) {
            const int kk = efq * 32 + j * 8;
            const int blk = kk >> 3;
            const uint32_t o = (uint32_t)efrow * 128 +
                               (uint32_t)((blk ^ (efrow & 7)) << 4);
            *(uint4*)(tb + o) = make_uint4(efreg[j * 4], efreg[j * 4 + 1],
                                           efreg[j * 4 + 2], efreg[j * 4 + 3]);
        }
    };
    // 64-wide-K subchunk: acc += X*W, 1-pass fp16, warp tile 32x64.
    auto compute_sub = [&](float (&acc)[2][8][4], uint32_t xbase, uint32_t wbase) {
#pragma unroll
        for (int ks = 0; ks < 4; ++ks) {
            const uint32_t oA = aRow + (uint32_t)((((2 * ks + aHi) ^ xA)) << 4);
            const uint32_t oB = bRow + (uint32_t)((((2 * ks + bHi) ^ xB)) << 4);
            uint32_t ah[2][4], bh[4][4];
            ldsm4(ah[0], xbase + oA);
            ldsm4(ah[1], xbase + oA + 2048);
#pragma unroll
            for (int nj = 0; nj < 4; ++nj)
                ldsm4(bh[nj], wbase + oB + nj * 2048);
#pragma unroll
            for (int mi = 0; mi < 2; ++mi)
#pragma unroll
                for (int nj = 0; nj < 4; ++nj) {
                    mma16816(acc[mi][2 * nj],     ah[mi], bh[nj][0], bh[nj][1]);
                    mma16816(acc[mi][2 * nj + 1], ah[mi], bh[nj][2], bh[nj][3]);
                }
        }
    };

    float acc[2][8][4];
#pragma unroll
    for (int mi = 0; mi < 2; ++mi)
#pragma unroll
        for (int ni = 0; ni < 8; ++ni)
#pragma unroll
            for (int r = 0; r < 4; ++r) acc[mi][ni][r] = 0.f;

    // ---------------- GEMM1: pipelined over S1 subchunks --------------------
    issueX(0, XB(0));
    CP_COMMIT();
    issueW(0, 0);
#pragma unroll
    for (int s = 0; s < S1; ++s) {
        CP_WAIT0();                              // X buf (s&1) ready
        mbar_wait(sb + MBAR_OFF + 8 * (s & 1), (s >> 1) & 1);   // W buf ready
        __syncthreads();
        const bool curEF = EDGE && (s >> 1) == 2;
        if (curEF) {
            stsEF(XB(s & 1));
            __syncthreads();
        }
        if (s + 1 < S1) {
            const bool nxtEF = EDGE && ((s + 1) >> 1) == 2;
            if (nxtEF) ldgEF(s + 1);
            else       issueX(s + 1, XB((s + 1) & 1));
            CP_COMMIT();
            issueW(s + 1, (s + 1) & 1);
        }
        compute_sub(acc, sb + XB(s & 1), sb + WB(s & 1));
        __syncthreads();
    }

    // ---------------- W2 prefetch (safe: all GEMM1 compute done) ------------
    issueW(S1, 0);
    issueW(S1 + 1, 1);

    // ---------------- epilogue 1: h = relu(y1+b1) -> H tiles ----------------
    {
        const float* s_b1 = (const float*)(smem + BIAS1_OFF);
#pragma unroll
        for (int mi = 0; mi < 2; ++mi) {
            const int r0 = wrow * 32 + mi * 16 + g, r1 = r0 + 8;
#pragma unroll
            for (int ni = 0; ni < 8; ++ni) {
                const int col = wcol * 64 + ni * 8 + t4 * 2;
                const float ba = s_b1[col], bb = s_b1[col + 1];
                float v0 = fmaxf(acc[mi][ni][0] + ba, 0.f);
                float v1 = fmaxf(acc[mi][ni][1] + bb, 0.f);
                float v2 = fmaxf(acc[mi][ni][2] + ba, 0.f);
                float v3 = fmaxf(acc[mi][ni][3] + bb, 0.f);
                uint32_t h0 = pack2h(v0, v1);
                uint32_t h1 = pack2h(v2, v3);
                const int sub = col >> 6, kk = col & 63;
                const int bblk = kk >> 3, w2 = (kk & 7) * 2;
                char* tb = smem + sub * 8192;     // H subchunk -> XB(sub)
                char* d0 = tb + r0 * 128 + (((bblk ^ (r0 & 7))) << 4) + w2;
                char* d1 = tb + r1 * 128 + (((bblk ^ (r1 & 7))) << 4) + w2;
                *(uint32_t*)d0 = h0;
                *(uint32_t*)d1 = h1;
            }
        }
        // reset accumulators for GEMM2 (register reuse)
#pragma unroll
        for (int mi = 0; mi < 2; ++mi)
#pragma unroll
            for (int ni = 0; ni < 8; ++ni)
#pragma unroll
                for (int r = 0; r < 4; ++r) acc[mi][ni][r] = 0.f;
    }
    mbar_wait(sb + MBAR_OFF, (S1 / 2) & 1);
    mbar_wait(sb + MBAR_OFF + 8, (S1 / 2) & 1);
    __syncthreads();

    // ---------------- GEMM2: 2 subchunks (H in XB0/XB1, W2 in WB0/WB1) ------
    compute_sub(acc, sb + XB(0), sb + WB(0));
    compute_sub(acc, sb + XB(1), sb + WB(1));

    // ---------------- epilogue 2: LayerNorm + residual + scatter ------------
    {
        const float* s_b2 = (const float*)(smem + BIAS2_OFF);
        float s[2][2] = {{0.f, 0.f}, {0.f, 0.f}};
        float ss[2][2] = {{0.f, 0.f}, {0.f, 0.f}};
#pragma unroll
        for (int mi = 0; mi < 2; ++mi)
#pragma unroll
            for (int ni = 0; ni < 8; ++ni) {
                const int col = wcol * 64 + ni * 8 + t4 * 2;
                const float ba = s_b2[col], bb = s_b2[col + 1];
                float y0 = acc[mi][ni][0] + ba, y1 = acc[mi][ni][1] + bb;
                float y2 = acc[mi][ni][2] + ba, y3 = acc[mi][ni][3] + bb;
                acc[mi][ni][0] = y0; acc[mi][ni][1] = y1;
                acc[mi][ni][2] = y2; acc[mi][ni][3] = y3;
                s[mi][0] += y0 + y1; ss[mi][0] += y0 * y0 + y1 * y1;
                s[mi][1] += y2 + y3; ss[mi][1] += y2 * y2 + y3 * y3;
            }
#pragma unroll
        for (int off = 1; off <= 2; off <<= 1)
#pragma unroll
            for (int mi = 0; mi < 2; ++mi)
#pragma unroll
                for (int h = 0; h < 2; ++h) {
                    s[mi][h] += __shfl_xor_sync(0xffffffffu, s[mi][h], off);
                    ss[mi][h] += __shfl_xor_sync(0xffffffffu, ss[mi][h], off);
                }
        float2* part = (float2*)(smem + PART_OFF);
        if (t4 == 0)
#pragma unroll
            for (int mi = 0; mi < 2; ++mi)
#pragma unroll
                for (int h = 0; h < 2; ++h) {
                    const int row = wrow * 32 + mi * 16 + g + h * 8;
                    part[row * 2 + wcol] = make_float2(s[mi][h], ss[mi][h]);
                }
        __syncthreads();

        const float* s_g = (const float*)(smem + GAM_OFF);
        const float* s_bb = (const float*)(smem + BET_OFF);
#pragma unroll
        for (int mi = 0; mi < 2; ++mi)
#pragma unroll
            for (int h = 0; h < 2; ++h) {
                const int row = wrow * 32 + mi * 16 + g + h * 8;
                if (row >= valid) continue;
                float2 p0 = part[row * 2], p1 = part[row * 2 + 1];
                const float mu = (p0.x + p1.x) * (1.f / 128.f);
                const float var = (p0.y + p1.y) * (1.f / 128.f) - mu * mu;
                const float inv = rsqrtf(var + LN_EPS);
                const size_t gro = (size_t)(base + row) * 128;
                const float* res = (EDGE ? ef : nf) + gro;
                float* op = out + gro;
                float* ap = nullptr;
                if (EDGE) {
                    const int rv = ((const int*)(smem + RIDX_OFF))[row];
                    ap = g_agg + (size_t)rv * 128;
                }
#pragma unroll
                for (int ni = 0; ni < 8; ++ni) {
                    const int col = wcol * 64 + ni * 8 + t4 * 2;
                    const float y0 = acc[mi][ni][h * 2];
                    const float y1 = acc[mi][ni][h * 2 + 1];
                    const float m0 = (y0 - mu) * inv * s_g[col] + s_bb[col];
                    const float m1 = (y1 - mu) * inv * s_g[col + 1] + s_bb[col + 1];
                    if (EDGE) red_add_v2(ap + col, m0, m1);
                    float2 r2 = *(const float2*)(res + col);
                    *(float2*)(op + col) = make_float2(m0 + r2.x, m1 + r2.y);
                }
            }
    }
}

// ---------------------------------------------------------------------------
extern "C" void kernel_launch(void* const* d_in, const int* in_sizes, int n_in,
                              void* d_out, int out_size) {
    const float* nf  = (const float*)d_in[0];
    const float* ef  = (const float*)d_in[1];
    const int*   snd = (const int*)d_in[2];
    const int*   rcv = (const int*)d_in[3];
    const float* We1 = (const float*)d_in[4];
    const float* be1 = (const float*)d_in[5];
    const float* We2 = (const float*)d_in[6];
    const float* be2 = (const float*)d_in[7];
    const float* ge  = (const float*)d_in[8];
    const float* bbe = (const float*)d_in[9];
    const float* Wn1 = (const float*)d_in[10];
    const float* bn1 = (const float*)d_in[11];
    const float* Wn2 = (const float*)d_in[12];
    const float* bn2 = (const float*)d_in[13];
    const float* gn  = (const float*)d_in[14];
    const float* bbn = (const float*)d_in[15];

    float* out_nodes = (float*)d_out;
    float* out_edges = out_nodes + (size_t)N_NODES * 128;

    cudaFuncSetAttribute(gnb_kernel<6, true>,
                         cudaFuncAttributeMaxDynamicSharedMemorySize, SMEM_TOTAL);
    cudaFuncSetAttribute(gnb_kernel<4, false>,
                         cudaFuncAttributeMaxDynamicSharedMemorySize, SMEM_TOTAL);

    prep_w<<<448, 256>>>(We1, We2, Wn1, Wn2);
    conv_nf_kernel<<<6250, 256>>>(nf);       // 50000*32 float4s
    zero_agg_kernel<<<6250, 256>>>();

    gnb_kernel<6, true><<<N_EDGES / 64, 128, SMEM_TOTAL>>>(
        nf, ef, snd, rcv, be1, be2, ge, bbe, out_edges);

    conv_agg_kernel<<<6250, 256>>>();

    gnb_kernel<4, false><<<(N_NODES + 63) / 64, 128, SMEM_TOTAL>>>(
        nf, nullptr, nullptr, nullptr, bn1, bn2, gn, bbn, out_nodes);
}

// round 16
// speedup vs baseline: 1.6189x; 1.0276x over previous
#include <cuda_runtime.h>
#include <cuda_fp16.h>
#include <cstdint>

#define N_NODES 50000
#define N_EDGES 600000
#define LN_EPS 1e-5f

// ---------------- device-global scratch (no allocations allowed) ------------
__device__ float g_agg[N_NODES * 128];
__device__ __half g_nf[N_NODES * 128];
// Weights per K-64 subchunk, PRE-SWIZZLED (ldmatrix XOR layout), 16KB each.
// Edge: sc 0-5 = We1 (K=384), 6-7 = We2. Node: sc 0-3 = Wn1, 4-5 = Wn2.
__device__ __align__(16) __half g_We[8 * 8192];
__device__ __align__(16) __half g_Wn[6 * 8192];

// ---------------- smem layout (bytes) ---------------------------------------
// X sub-tile buf: 64 rows x 128B (fp16). Two bufs (cp.async double-buffered).
// W sub-tile buf: 128 rows x 128B (fp16). Two bufs (bulk-DMA filled).
#define XB(i)     ((uint32_t)(i) * 8192u)
#define WB(i)     (16384u + (uint32_t)(i) * 16384u)
#define BIAS1_OFF 49152
#define BIAS2_OFF 49664
#define GAM_OFF   50176
#define BET_OFF   50688
#define SIDX_OFF  51200
#define RIDX_OFF  51456
#define PART_OFF  51712
#define MBAR_OFF  53760          // 2 x 8B mbarriers for W bulk copies
#define SMEM_TOTAL 53824

// ---------------- helpers ----------------------------------------------------
__device__ __forceinline__ uint32_t smem_u32(const void* p) {
    uint32_t a;
    asm("{ .reg .u64 t; cvta.to.shared.u64 t, %1; cvt.u32.u64 %0, t; }"
        : "=r"(a) : "l"(p));
    return a;
}
__device__ __forceinline__ void ldsm4(uint32_t (&r)[4], uint32_t a) {
    asm volatile("ldmatrix.sync.aligned.m8n8.x4.shared.b16 {%0,%1,%2,%3}, [%4];"
                 : "=r"(r[0]), "=r"(r[1]), "=r"(r[2]), "=r"(r[3]) : "r"(a));
}
__device__ __forceinline__ void mma16816(float (&d)[4], const uint32_t (&a)[4],
                                         uint32_t b0, uint32_t b1) {
    asm volatile(
        "mma.sync.aligned.m16n8k16.row.col.f32.f16.f16.f32 "
        "{%0,%1,%2,%3}, {%4,%5,%6,%7}, {%8,%9}, {%0,%1,%2,%3};"
        : "+f"(d[0]), "+f"(d[1]), "+f"(d[2]), "+f"(d[3])
        : "r"(a[0]), "r"(a[1]), "r"(a[2]), "r"(a[3]), "r"(b0), "r"(b1));
}
__device__ __forceinline__ void red_add_v2(float* p, float a, float b) {
    asm volatile("red.global.add.v2.f32 [%0], {%1, %2};"
                 :: "l"(p), "f"(a), "f"(b) : "memory");
}
__device__ __forceinline__ void cp_async16z(uint32_t d, const void* s, uint32_t sz) {
    asm volatile("cp.async.cg.shared.global [%0], [%1], 16, %2;"
                 :: "r"(d), "l"(s), "r"(sz) : "memory");
}
#define CP_COMMIT() asm volatile("cp.async.commit_group;" ::: "memory")
#define CP_WAIT0()  asm volatile("cp.async.wait_group 0;" ::: "memory")

__device__ __forceinline__ void mbar_init(uint32_t a, uint32_t c) {
    asm volatile("mbarrier.init.shared.b64 [%0], %1;" :: "r"(a), "r"(c) : "memory");
}
__device__ __forceinline__ void mbar_expect(uint32_t a, uint32_t bytes) {
    asm volatile("mbarrier.arrive.expect_tx.shared.b64 _, [%0], %1;"
                 :: "r"(a), "r"(bytes) : "memory");
}
__device__ __forceinline__ void bulk_g2s(uint32_t dst, const void* src,
                                         uint32_t bytes, uint32_t mbar) {
    asm volatile(
        "cp.async.bulk.shared::cta.global.mbarrier::complete_tx::bytes "
        "[%0], [%1], %2, [%3];"
        :: "r"(dst), "l"(src), "r"(bytes), "r"(mbar) : "memory");
}
__device__ __forceinline__ void mbar_wait(uint32_t addr, uint32_t parity) {
    uint32_t done;
    do {
        asm volatile(
            "{\n\t.reg .pred P;\n\t"
            "mbarrier.try_wait.parity.acquire.cta.shared::cta.b64 P, [%1], %2, 0x989680;\n\t"
            "selp.b32 %0, 1, 0, P;\n\t}"
            : "=r"(done) : "r"(addr), "r"(parity) : "memory");
    } while (!done);
}

// pack two fp32 -> fp16x2
__device__ __forceinline__ uint32_t pack2h(float a, float b) {
    __half2 h = __floats2half2_rn(a, b);
    return *(uint32_t*)&h;
}

// ---------------- utility kernels (device symbols referenced in DEVICE code) -
__global__ void zero_agg_kernel() {
    int i = blockIdx.x * blockDim.x + threadIdx.x;
    ((float4*)g_agg)[i] = make_float4(0.f, 0.f, 0.f, 0.f);
}
__global__ void conv_nf_kernel(const float* __restrict__ src) {
    int i = blockIdx.x * blockDim.x + threadIdx.x;   // N_NODES*32 float4s
    float4 v = ((const float4*)src)[i];
    ((uint2*)g_nf)[i] = make_uint2(pack2h(v.x, v.y), pack2h(v.z, v.w));
}
// Write W pre-swizzled: element (n, kk) -> byte n*128 + ((kk>>3 ^ (n&7))<<4) + (kk&7)*2
__global__ void prep_w(const float* __restrict__ We1, const float* __restrict__ We2,
                       const float* __restrict__ Wn1, const float* __restrict__ Wn2) {
    int idx = blockIdx.x * blockDim.x + threadIdx.x;
    if (idx >= 114688) return;
    char* dst;
    float v;
    int n, kk;
    if (idx < 65536) {
        int sc = idx >> 13, rem = idx & 8191;
        n = rem >> 6; kk = rem & 63;
        v = (sc < 6) ? We1[(sc * 64 + kk) * 128 + n] : We2[((sc - 6) * 64 + kk) * 128 + n];
        dst = (char*)(g_We + sc * 8192);
    } else {
        int j = idx - 65536;
        int sc = j >> 13, rem = j & 8191;
        n = rem >> 6; kk = rem & 63;
        v = (sc < 4) ? Wn1[(sc * 64 + kk) * 128 + n] : Wn2[((sc - 4) * 64 + kk) * 128 + n];
        dst = (char*)(g_Wn + sc * 8192);
    }
    uint32_t off = (uint32_t)n * 128 + (uint32_t)(((kk >> 3) ^ (n & 7)) << 4) +
                   (uint32_t)(kk & 7) * 2;
    *(__half*)(dst + off) = __float2half_rn(v);
}

// ---------------- main fused tile kernel -------------------------------------
// 256 threads, 3 CTAs/SM, 2x4 warp grid (warp tile 32x32), M tile 64.
// 1-pass fp16 GEMM. W via cp.async.bulk (pre-swizzled global). X via cp.async
// double-buffer. fp32 sources (EDGE: ef chunk; NODE: agg chunk) convert inline
// via LDG prefetch (one subchunk ahead) + cvt-on-arrival + STS.128.
template <int S1, bool EDGE>
__global__ void __launch_bounds__(256, 3)
gnb_kernel(const float* __restrict__ nf, const float* __restrict__ ef,
           const int* __restrict__ snd, const int* __restrict__ rcv,
           const float* __restrict__ b1, const float* __restrict__ b2,
           const float* __restrict__ gam, const float* __restrict__ bet,
           float* __restrict__ out) {
    extern __shared__ char smem[];
    const uint32_t sb = smem_u32(smem);
    const int tid = threadIdx.x, lane = tid & 31, wid = tid >> 5;
    const int wrow = wid >> 2, wcol = wid & 3;
    const int base = blockIdx.x * 64;
    const int total = EDGE ? N_EDGES : N_NODES;
    const int valid = min(64, total - base);
    const int F32CS = EDGE ? 2 : 1;              // fp32-source chunk index

    if (tid == 0) {
        mbar_init(sb + MBAR_OFF, 1);
        mbar_init(sb + MBAR_OFF + 8, 1);
    }
    if (tid < 128) {
        ((float*)(smem + BIAS1_OFF))[tid] = b1[tid];
        ((float*)(smem + BIAS2_OFF))[tid] = b2[tid];
        ((float*)(smem + GAM_OFF))[tid] = gam[tid];
        ((float*)(smem + BET_OFF))[tid] = bet[tid];
    }
    if (EDGE && tid < 64) {
        ((int*)(smem + SIDX_OFF))[tid] = (tid < valid) ? snd[base + tid] : 0;
        ((int*)(smem + RIDX_OFF))[tid] = (tid < valid) ? rcv[base + tid] : 0;
    }
    __syncthreads();

    // per-lane ldsm constants (swizzled: block b at row r lives at (b ^ (r&7))*16)
    const int aHi = lane >> 4;
    const int rA = wrow * 32 + (lane & 15);
    const int xA = rA & 7;
    const uint32_t aRow = (uint32_t)rA * 128;
    const int bHi = (lane >> 3) & 1;
    const int rB = wcol * 32 + (lane & 7) + ((lane >> 4) << 3);
    const int xB = rB & 7;
    const uint32_t bRow = (uint32_t)rB * 128;
    const int g = lane >> 2, t4 = lane & 3;

    // bulk W load: one DMA per 16KB subchunk (pre-swizzled in global)
    auto issueW = [&](int sc, int buf) {
        if (tid == 0) {
            const __half* gW = EDGE ? g_We : g_Wn;
            mbar_expect(sb + MBAR_OFF + 8 * buf, 16384u);
            bulk_g2s(sb + WB(buf), gW + sc * 8192, 16384u, sb + MBAR_OFF + 8 * buf);
        }
    };
    auto issueX = [&](int s, uint32_t xoff) {
        const int cs = s >> 1, kh = s & 1;
#pragma unroll
        for (int p = 0; p < 2; ++p) {
            int m = p * 256 + tid;                  // 512 16B chunks
            int row = m >> 3, b = m & 7;
            int gr;
            if (EDGE) {
                gr = ((const int*)(smem + (cs == 0 ? SIDX_OFF : RIDX_OFF)))[row];
            } else {
                gr = base + row;
                if (gr >= total) gr = total - 1;
            }
            const __half* src = g_nf + (size_t)gr * 128 + kh * 64 + b * 8;
            uint32_t dst = sb + xoff + (uint32_t)row * 128 +
                           (uint32_t)((b ^ (row & 7)) << 4);
            cp_async16z(dst, src, (row < valid) ? 16u : 0u);
        }
    };
    // fp32-source prefetch (coalesced stream, one subchunk ahead), cvt on arrival
    uint32_t freg[8];
    const int frow = tid >> 2, fq = tid & 3;
    auto ldgF = [&](int s) {
        const int kh = s & 1;
        const float* srcb = EDGE ? ef : g_agg;
        const float* src = srcb + (size_t)(base + frow) * 128 + kh * 64 + fq * 16;
        const bool ok = frow < valid;
#pragma unroll
        for (int j = 0; j < 4; ++j) {
            float4 v = ok ? ((const float4*)src)[j] : make_float4(0.f, 0.f, 0.f, 0.f);
            freg[j * 2]     = pack2h(v.x, v.y);
            freg[j * 2 + 1] = pack2h(v.z, v.w);
        }
    };
    auto stsF = [&](uint32_t xoff) {
        char* tb = smem + xoff;
#pragma unroll
        for (int j = 0; j < 2; ++j) {
            const int kk = fq * 16 + j * 8;
            const int blk = kk >> 3;
            const uint32_t o = (uint32_t)frow * 128 +
                               (uint32_t)((blk ^ (frow & 7)) << 4);
            *(uint4*)(tb + o) = make_uint4(freg[j * 4], freg[j * 4 + 1],
                                           freg[j * 4 + 2], freg[j * 4 + 3]);
        }
    };
    // 64-wide-K subchunk: acc += X*W, 1-pass fp16.
    auto compute_sub = [&](float (&acc)[2][4][4], uint32_t xbase, uint32_t wbase) {
#pragma unroll
        for (int ks = 0; ks < 4; ++ks) {
            const uint32_t oA = aRow + (uint32_t)((((2 * ks + aHi) ^ xA)) << 4);
            const uint32_t oB = bRow + (uint32_t)((((2 * ks + bHi) ^ xB)) << 4);
            uint32_t ah[2][4], bh[2][4];
            ldsm4(ah[0], xbase + oA);
            ldsm4(ah[1], xbase + oA + 2048);
            ldsm4(bh[0], wbase + oB);
            ldsm4(bh[1], wbase + oB + 2048);
#pragma unroll
            for (int mi = 0; mi < 2; ++mi)
#pragma unroll
                for (int nj = 0; nj < 2; ++nj) {
                    mma16816(acc[mi][2 * nj],     ah[mi], bh[nj][0], bh[nj][1]);
                    mma16816(acc[mi][2 * nj + 1], ah[mi], bh[nj][2], bh[nj][3]);
                }
        }
    };

    float acc[2][4][4];
#pragma unroll
    for (int mi = 0; mi < 2; ++mi)
#pragma unroll
        for (int ni = 0; ni < 4; ++ni)
#pragma unroll
            for (int r = 0; r < 4; ++r) acc[mi][ni][r] = 0.f;

    // ---------------- GEMM1: pipelined over S1 subchunks --------------------
    issueX(0, XB(0));
    CP_COMMIT();
    issueW(0, 0);
#pragma unroll
    for (int s = 0; s < S1; ++s) {
        CP_WAIT0();                              // X buf (s&1) ready
        mbar_wait(sb + MBAR_OFF + 8 * (s & 1), (s >> 1) & 1);   // W buf ready
        __syncthreads();                         // also: prev compute done
        if ((s >> 1) == F32CS) {
            stsF(XB(s & 1));
            __syncthreads();
        }
        if (s + 1 < S1) {
            if (((s + 1) >> 1) == F32CS) ldgF(s + 1);
            else                         issueX(s + 1, XB((s + 1) & 1));
            CP_COMMIT();
            issueW(s + 1, (s + 1) & 1);
        }
        compute_sub(acc, sb + XB(s & 1), sb + WB(s & 1));
    }
    __syncthreads();                             // all GEMM1 reads done

    // ---------------- W2 prefetch (safe: all GEMM1 compute done) ------------
    issueW(S1, 0);
    issueW(S1 + 1, 1);

    // ---------------- epilogue 1: h = relu(y1+b1) -> H tiles ----------------
    {
        const float* s_b1 = (const float*)(smem + BIAS1_OFF);
#pragma unroll
        for (int mi = 0; mi < 2; ++mi) {
            const int r0 = wrow * 32 + mi * 16 + g, r1 = r0 + 8;
#pragma unroll
            for (int ni = 0; ni < 4; ++ni) {
                const int col = wcol * 32 + ni * 8 + t4 * 2;
                const float ba = s_b1[col], bb = s_b1[col + 1];
                float v0 = fmaxf(acc[mi][ni][0] + ba, 0.f);
                float v1 = fmaxf(acc[mi][ni][1] + bb, 0.f);
                float v2 = fmaxf(acc[mi][ni][2] + ba, 0.f);
                float v3 = fmaxf(acc[mi][ni][3] + bb, 0.f);
                uint32_t h0 = pack2h(v0, v1);
                uint32_t h1 = pack2h(v2, v3);
                const int sub = col >> 6, kk = col & 63;
                const int bblk = kk >> 3, w2 = (kk & 7) * 2;
                char* tb = smem + sub * 8192;     // H subchunk -> XB(sub)
                char* d0 = tb + r0 * 128 + (((bblk ^ (r0 & 7))) << 4) + w2;
                char* d1 = tb + r1 * 128 + (((bblk ^ (r1 & 7))) << 4) + w2;
                *(uint32_t*)d0 = h0;
                *(uint32_t*)d1 = h1;
            }
        }
        // reset accumulators for GEMM2 (register reuse)
#pragma unroll
        for (int mi = 0; mi < 2; ++mi)
#pragma unroll
            for (int ni = 0; ni < 4; ++ni)
#pragma unroll
                for (int r = 0; r < 4; ++r) acc[mi][ni][r] = 0.f;
    }
    mbar_wait(sb + MBAR_OFF, (S1 / 2) & 1);
    mbar_wait(sb + MBAR_OFF + 8, (S1 / 2) & 1);
    __syncthreads();

    // ---------------- GEMM2: 2 subchunks (H in XB0/XB1, W2 in WB0/WB1) ------
    compute_sub(acc, sb + XB(0), sb + WB(0));
    compute_sub(acc, sb + XB(1), sb + WB(1));

    // ---------------- epilogue 2: LayerNorm + residual + scatter ------------
    {
        const float* s_b2 = (const float*)(smem + BIAS2_OFF);
        float s[2][2] = {{0.f, 0.f}, {0.f, 0.f}};
        float ss[2][2] = {{0.f, 0.f}, {0.f, 0.f}};
#pragma unroll
        for (int mi = 0; mi < 2; ++mi)
#pragma unroll
            for (int ni = 0; ni < 4; ++ni) {
                const int col = wcol * 32 + ni * 8 + t4 * 2;
                const float ba = s_b2[col], bb = s_b2[col + 1];
                float y0 = acc[mi][ni][0] + ba, y1 = acc[mi][ni][1] + bb;
                float y2 = acc[mi][ni][2] + ba, y3 = acc[mi][ni][3] + bb;
                acc[mi][ni][0] = y0; acc[mi][ni][1] = y1;
                acc[mi][ni][2] = y2; acc[mi][ni][3] = y3;
                s[mi][0] += y0 + y1; ss[mi][0] += y0 * y0 + y1 * y1;
                s[mi][1] += y2 + y3; ss[mi][1] += y2 * y2 + y3 * y3;
            }
#pragma unroll
        for (int off = 1; off <= 2; off <<= 1)
#pragma unroll
            for (int mi = 0; mi < 2; ++mi)
#pragma unroll
                for (int h = 0; h < 2; ++h) {
                    s[mi][h] += __shfl_xor_sync(0xffffffffu, s[mi][h], off);
                    ss[mi][h] += __shfl_xor_sync(0xffffffffu, ss[mi][h], off);
                }
        float2* part = (float2*)(smem + PART_OFF);
        if (t4 == 0)
#pragma unroll
            for (int mi = 0; mi < 2; ++mi)
#pragma unroll
                for (int h = 0; h < 2; ++h) {
                    const int row = wrow * 32 + mi * 16 + g + h * 8;
                    part[row * 4 + wcol] = make_float2(s[mi][h], ss[mi][h]);
                }
        __syncthreads();

        const float* s_g = (const float*)(smem + GAM_OFF);
        const float* s_bb = (const float*)(smem + BET_OFF);
#pragma unroll
        for (int mi = 0; mi < 2; ++mi)
#pragma unroll
            for (int h = 0; h < 2; ++h) {
                const int row = wrow * 32 + mi * 16 + g + h * 8;
                if (row >= valid) continue;
                float2 p0 = part[row * 4], p1 = part[row * 4 + 1];
                float2 p2 = part[row * 4 + 2], p3 = part[row * 4 + 3];
                const float mu = (p0.x + p1.x + p2.x + p3.x) * (1.f / 128.f);
                const float var =
                    (p0.y + p1.y + p2.y + p3.y) * (1.f / 128.f) - mu * mu;
                const float inv = rsqrtf(var + LN_EPS);
                const size_t gro = (size_t)(base + row) * 128;
                const float* res = (EDGE ? ef : nf) + gro;
                float* op = out + gro;
                float* ap = nullptr;
                if (EDGE) {
                    const int rv = ((const int*)(smem + RIDX_OFF))[row];
                    ap = g_agg + (size_t)rv * 128;
                }
#pragma unroll
                for (int ni = 0; ni < 4; ++ni) {
                    const int col = wcol * 32 + ni * 8 + t4 * 2;
                    const float y0 = acc[mi][ni][h * 2];
                    const float y1 = acc[mi][ni][h * 2 + 1];
                    const float m0 = (y0 - mu) * inv * s_g[col] + s_bb[col];
                    const float m1 = (y1 - mu) * inv * s_g[col + 1] + s_bb[col + 1];
                    if (EDGE) red_add_v2(ap + col, m0, m1);
                    float2 r2 = *(const float2*)(res + col);
                    *(float2*)(op + col) = make_float2(m0 + r2.x, m1 + r2.y);
                }
            }
    }
}

// ---------------------------------------------------------------------------
extern "C" void kernel_launch(void* const* d_in, const int* in_sizes, int n_in,
                              void* d_out, int out_size) {
    const float* nf  = (const float*)d_in[0];
    const float* ef  = (const float*)d_in[1];
    const int*   snd = (const int*)d_in[2];
    const int*   rcv = (const int*)d_in[3];
    const float* We1 = (const float*)d_in[4];
    const float* be1 = (const float*)d_in[5];
    const float* We2 = (const float*)d_in[6];
    const float* be2 = (const float*)d_in[7];
    const float* ge  = (const float*)d_in[8];
    const float* bbe = (const float*)d_in[9];
    const float* Wn1 = (const float*)d_in[10];
    const float* bn1 = (const float*)d_in[11];
    const float* Wn2 = (const float*)d_in[12];
    const float* bn2 = (const float*)d_in[13];
    const float* gn  = (const float*)d_in[14];
    const float* bbn = (const float*)d_in[15];

    float* out_nodes = (float*)d_out;
    float* out_edges = out_nodes + (size_t)N_NODES * 128;

    cudaFuncSetAttribute(gnb_kernel<6, true>,
                         cudaFuncAttributeMaxDynamicSharedMemorySize, SMEM_TOTAL);
    cudaFuncSetAttribute(gnb_kernel<4, false>,
                         cudaFuncAttributeMaxDynamicSharedMemorySize, SMEM_TOTAL);

    prep_w<<<448, 256>>>(We1, We2, Wn1, Wn2);
    conv_nf_kernel<<<6250, 256>>>(nf);       // 50000*32 float4s
    zero_agg_kernel<<<6250, 256>>>();

    gnb_kernel<6, true><<<N_EDGES / 64, 256, SMEM_TOTAL>>>(
        nf, ef, snd, rcv, be1, be2, ge, bbe, out_edges);

    gnb_kernel<4, false><<<(N_NODES + 63) / 64, 256, SMEM_TOTAL>>>(
        nf, nullptr, nullptr, nullptr, bn1, bn2, gn, bbn, out_nodes);
}

// round 17
// speedup vs baseline: 1.7215x; 1.0634x over previous
#include <cuda_runtime.h>
#include <cuda_fp16.h>
#include <cstdint>

#define N_NODES 50000
#define N_EDGES 600000
#define LN_EPS 1e-5f

// ---------------- device-global scratch (no allocations allowed) ------------
__device__ float g_agg[N_NODES * 128];
__device__ __half g_nf[N_NODES * 128];
// Weights per K-64 subchunk, PRE-SWIZZLED (ldmatrix XOR layout), 16KB each.
// Edge: sc 0-5 = We1 (K=384), 6-7 = We2. Node: sc 0-3 = Wn1, 4-5 = Wn2.
__device__ __align__(16) __half g_We[8 * 8192];
__device__ __align__(16) __half g_Wn[6 * 8192];

// ---------------- smem layout (bytes) ---------------------------------------
// X sub-tile buf: 64 rows x 128B (fp16). Two bufs (cp.async double-buffered).
// W sub-tile buf: 128 rows x 128B (fp16). Two bufs (bulk-DMA filled).
// After GEMM2, bytes [0, 33792) are reused as the fp32 m-tile (64 x 132 floats).
#define XB(i)     ((uint32_t)(i) * 8192u)
#define WB(i)     (16384u + (uint32_t)(i) * 16384u)
#define MT_STRIDE 132                    // floats per m-tile row (bank-spread pad)
#define BIAS1_OFF 49152
#define BIAS2_OFF 49664
#define GAM_OFF   50176
#define BET_OFF   50688
#define SIDX_OFF  51200
#define RIDX_OFF  51456
#define PART_OFF  51712
#define MBAR_OFF  53760          // 2 x 8B mbarriers for W bulk copies
#define SMEM_TOTAL 53824

// ---------------- helpers ----------------------------------------------------
__device__ __forceinline__ uint32_t smem_u32(const void* p) {
    uint32_t a;
    asm("{ .reg .u64 t; cvta.to.shared.u64 t, %1; cvt.u32.u64 %0, t; }"
        : "=r"(a) : "l"(p));
    return a;
}
__device__ __forceinline__ void ldsm4(uint32_t (&r)[4], uint32_t a) {
    asm volatile("ldmatrix.sync.aligned.m8n8.x4.shared.b16 {%0,%1,%2,%3}, [%4];"
                 : "=r"(r[0]), "=r"(r[1]), "=r"(r[2]), "=r"(r[3]) : "r"(a));
}
__device__ __forceinline__ void mma16816(float (&d)[4], const uint32_t (&a)[4],
                                         uint32_t b0, uint32_t b1) {
    asm volatile(
        "mma.sync.aligned.m16n8k16.row.col.f32.f16.f16.f32 "
        "{%0,%1,%2,%3}, {%4,%5,%6,%7}, {%8,%9}, {%0,%1,%2,%3};"
        : "+f"(d[0]), "+f"(d[1]), "+f"(d[2]), "+f"(d[3])
        : "r"(a[0]), "r"(a[1]), "r"(a[2]), "r"(a[3]), "r"(b0), "r"(b1));
}
__device__ __forceinline__ void red_add_v2(float* p, float a, float b) {
    asm volatile("red.global.add.v2.f32 [%0], {%1, %2};"
                 :: "l"(p), "f"(a), "f"(b) : "memory");
}
__device__ __forceinline__ void cp_async16z(uint32_t d, const void* s, uint32_t sz) {
    asm volatile("cp.async.cg.shared.global [%0], [%1], 16, %2;"
                 :: "r"(d), "l"(s), "r"(sz) : "memory");
}
#define CP_COMMIT() asm volatile("cp.async.commit_group;" ::: "memory")
#define CP_WAIT0()  asm volatile("cp.async.wait_group 0;" ::: "memory")

__device__ __forceinline__ void mbar_init(uint32_t a, uint32_t c) {
    asm volatile("mbarrier.init.shared.b64 [%0], %1;" :: "r"(a), "r"(c) : "memory");
}
__device__ __forceinline__ void mbar_expect(uint32_t a, uint32_t bytes) {
    asm volatile("mbarrier.arrive.expect_tx.shared.b64 _, [%0], %1;"
                 :: "r"(a), "r"(bytes) : "memory");
}
__device__ __forceinline__ void bulk_g2s(uint32_t dst, const void* src,
                                         uint32_t bytes, uint32_t mbar) {
    asm volatile(
        "cp.async.bulk.shared::cta.global.mbarrier::complete_tx::bytes "
        "[%0], [%1], %2, [%3];"
        :: "r"(dst), "l"(src), "r"(bytes), "r"(mbar) : "memory");
}
__device__ __forceinline__ void mbar_wait(uint32_t addr, uint32_t parity) {
    uint32_t done;
    do {
        asm volatile(
            "{\n\t.reg .pred P;\n\t"
            "mbarrier.try_wait.parity.acquire.cta.shared::cta.b64 P, [%1], %2, 0x989680;\n\t"
            "selp.b32 %0, 1, 0, P;\n\t}"
            : "=r"(done) : "r"(addr), "r"(parity) : "memory");
    } while (!done);
}

// pack two fp32 -> fp16x2
__device__ __forceinline__ uint32_t pack2h(float a, float b) {
    __half2 h = __floats2half2_rn(a, b);
    return *(uint32_t*)&h;
}

// ---------------- utility kernels (device symbols referenced in DEVICE code) -
__global__ void zero_agg_kernel() {
    int i = blockIdx.x * blockDim.x + threadIdx.x;
    ((float4*)g_agg)[i] = make_float4(0.f, 0.f, 0.f, 0.f);
}
__global__ void conv_nf_kernel(const float* __restrict__ src) {
    int i = blockIdx.x * blockDim.x + threadIdx.x;   // N_NODES*32 float4s
    float4 v = ((const float4*)src)[i];
    ((uint2*)g_nf)[i] = make_uint2(pack2h(v.x, v.y), pack2h(v.z, v.w));
}
// Write W pre-swizzled: element (n, kk) -> byte n*128 + ((kk>>3 ^ (n&7))<<4) + (kk&7)*2
__global__ void prep_w(const float* __restrict__ We1, const float* __restrict__ We2,
                       const float* __restrict__ Wn1, const float* __restrict__ Wn2) {
    int idx = blockIdx.x * blockDim.x + threadIdx.x;
    if (idx >= 114688) return;
    char* dst;
    float v;
    int n, kk;
    if (idx < 65536) {
        int sc = idx >> 13, rem = idx & 8191;
        n = rem >> 6; kk = rem & 63;
        v = (sc < 6) ? We1[(sc * 64 + kk) * 128 + n] : We2[((sc - 6) * 64 + kk) * 128 + n];
        dst = (char*)(g_We + sc * 8192);
    } else {
        int j = idx - 65536;
        int sc = j >> 13, rem = j & 8191;
        n = rem >> 6; kk = rem & 63;
        v = (sc < 4) ? Wn1[(sc * 64 + kk) * 128 + n] : Wn2[((sc - 4) * 64 + kk) * 128 + n];
        dst = (char*)(g_Wn + sc * 8192);
    }
    uint32_t off = (uint32_t)n * 128 + (uint32_t)(((kk >> 3) ^ (n & 7)) << 4) +
                   (uint32_t)(kk & 7) * 2;
    *(__half*)(dst + off) = __float2half_rn(v);
}

// ---------------- main fused tile kernel -------------------------------------
// 256 threads, 3 CTAs/SM, 2x4 warp grid (warp tile 32x32), M tile 64.
// 1-pass fp16 GEMM. W via cp.async.bulk (pre-swizzled global). X via cp.async
// double-buffer. fp32 sources (EDGE: ef chunk; NODE: agg chunk) convert inline.
// Epilogue-2 stages m in smem, then a row-coalesced LDG/STG/REDG pass.
template <int S1, bool EDGE>
__global__ void __launch_bounds__(256, 3)
gnb_kernel(const float* __restrict__ nf, const float* __restrict__ ef,
           const int* __restrict__ snd, const int* __restrict__ rcv,
           const float* __restrict__ b1, const float* __restrict__ b2,
           const float* __restrict__ gam, const float* __restrict__ bet,
           float* __restrict__ out) {
    extern __shared__ char smem[];
    const uint32_t sb = smem_u32(smem);
    const int tid = threadIdx.x, lane = tid & 31, wid = tid >> 5;
    const int wrow = wid >> 2, wcol = wid & 3;
    const int base = blockIdx.x * 64;
    const int total = EDGE ? N_EDGES : N_NODES;
    const int valid = min(64, total - base);
    const int F32CS = EDGE ? 2 : 1;              // fp32-source chunk index

    if (tid == 0) {
        mbar_init(sb + MBAR_OFF, 1);
        mbar_init(sb + MBAR_OFF + 8, 1);
    }
    if (tid < 128) {
        ((float*)(smem + BIAS1_OFF))[tid] = b1[tid];
        ((float*)(smem + BIAS2_OFF))[tid] = b2[tid];
        ((float*)(smem + GAM_OFF))[tid] = gam[tid];
        ((float*)(smem + BET_OFF))[tid] = bet[tid];
    }
    if (EDGE && tid < 64) {
        ((int*)(smem + SIDX_OFF))[tid] = (tid < valid) ? snd[base + tid] : 0;
        ((int*)(smem + RIDX_OFF))[tid] = (tid < valid) ? rcv[base + tid] : 0;
    }
    __syncthreads();

    // per-lane ldsm constants (swizzled: block b at row r lives at (b ^ (r&7))*16)
    const int aHi = lane >> 4;
    const int rA = wrow * 32 + (lane & 15);
    const int xA = rA & 7;
    const uint32_t aRow = (uint32_t)rA * 128;
    const int bHi = (lane >> 3) & 1;
    const int rB = wcol * 32 + (lane & 7) + ((lane >> 4) << 3);
    const int xB = rB & 7;
    const uint32_t bRow = (uint32_t)rB * 128;
    const int g = lane >> 2, t4 = lane & 3;

    // bulk W load: one DMA per 16KB subchunk (pre-swizzled in global)
    auto issueW = [&](int sc, int buf) {
        if (tid == 0) {
            const __half* gW = EDGE ? g_We : g_Wn;
            mbar_expect(sb + MBAR_OFF + 8 * buf, 16384u);
            bulk_g2s(sb + WB(buf), gW + sc * 8192, 16384u, sb + MBAR_OFF + 8 * buf);
        }
    };
    auto issueX = [&](int s, uint32_t xoff) {
        const int cs = s >> 1, kh = s & 1;
#pragma unroll
        for (int p = 0; p < 2; ++p) {
            int m = p * 256 + tid;                  // 512 16B chunks
            int row = m >> 3, b = m & 7;
            int gr;
            if (EDGE) {
                gr = ((const int*)(smem + (cs == 0 ? SIDX_OFF : RIDX_OFF)))[row];
            } else {
                gr = base + row;
                if (gr >= total) gr = total - 1;
            }
            const __half* src = g_nf + (size_t)gr * 128 + kh * 64 + b * 8;
            uint32_t dst = sb + xoff + (uint32_t)row * 128 +
                           (uint32_t)((b ^ (row & 7)) << 4);
            cp_async16z(dst, src, (row < valid) ? 16u : 0u);
        }
    };
    // fp32-source prefetch (coalesced stream, one subchunk ahead), cvt on arrival
    uint32_t freg[8];
    const int frow = tid >> 2, fq = tid & 3;
    auto ldgF = [&](int s) {
        const int kh = s & 1;
        const float* srcb = EDGE ? ef : g_agg;
        const float* src = srcb + (size_t)(base + frow) * 128 + kh * 64 + fq * 16;
        const bool ok = frow < valid;
#pragma unroll
        for (int j = 0; j < 4; ++j) {
            float4 v = ok ? ((const float4*)src)[j] : make_float4(0.f, 0.f, 0.f, 0.f);
            freg[j * 2]     = pack2h(v.x, v.y);
            freg[j * 2 + 1] = pack2h(v.z, v.w);
        }
    };
    auto stsF = [&](uint32_t xoff) {
        char* tb = smem + xoff;
#pragma unroll
        for (int j = 0; j < 2; ++j) {
            const int kk = fq * 16 + j * 8;
            const int blk = kk >> 3;
            const uint32_t o = (uint32_t)frow * 128 +
                               (uint32_t)((blk ^ (frow & 7)) << 4);
            *(uint4*)(tb + o) = make_uint4(freg[j * 4], freg[j * 4 + 1],
                                           freg[j * 4 + 2], freg[j * 4 + 3]);
        }
    };
    // 64-wide-K subchunk: acc += X*W, 1-pass fp16.
    auto compute_sub = [&](float (&acc)[2][4][4], uint32_t xbase, uint32_t wbase) {
#pragma unroll
        for (int ks = 0; ks < 4; ++ks) {
            const uint32_t oA = aRow + (uint32_t)((((2 * ks + aHi) ^ xA)) << 4);
            const uint32_t oB = bRow + (uint32_t)((((2 * ks + bHi) ^ xB)) << 4);
            uint32_t ah[2][4], bh[2][4];
            ldsm4(ah[0], xbase + oA);
            ldsm4(ah[1], xbase + oA + 2048);
            ldsm4(bh[0], wbase + oB);
            ldsm4(bh[1], wbase + oB + 2048);
#pragma unroll
            for (int mi = 0; mi < 2; ++mi)
#pragma unroll
                for (int nj = 0; nj < 2; ++nj) {
                    mma16816(acc[mi][2 * nj],     ah[mi], bh[nj][0], bh[nj][1]);
                    mma16816(acc[mi][2 * nj + 1], ah[mi], bh[nj][2], bh[nj][3]);
                }
        }
    };

    float acc[2][4][4];
#pragma unroll
    for (int mi = 0; mi < 2; ++mi)
#pragma unroll
        for (int ni = 0; ni < 4; ++ni)
#pragma unroll
            for (int r = 0; r < 4; ++r) acc[mi][ni][r] = 0.f;

    // ---------------- GEMM1: pipelined over S1 subchunks --------------------
    issueX(0, XB(0));
    CP_COMMIT();
    issueW(0, 0);
#pragma unroll
    for (int s = 0; s < S1; ++s) {
        CP_WAIT0();                              // X buf (s&1) ready
        mbar_wait(sb + MBAR_OFF + 8 * (s & 1), (s >> 1) & 1);   // W buf ready
        __syncthreads();                         // also: prev compute done
        if ((s >> 1) == F32CS) {
            stsF(XB(s & 1));
            __syncthreads();
        }
        if (s + 1 < S1) {
            if (((s + 1) >> 1) == F32CS) ldgF(s + 1);
            else                         issueX(s + 1, XB((s + 1) & 1));
            CP_COMMIT();
            issueW(s + 1, (s + 1) & 1);
        }
        compute_sub(acc, sb + XB(s & 1), sb + WB(s & 1));
    }
    __syncthreads();                             // all GEMM1 reads done

    // ---------------- W2 prefetch (safe: all GEMM1 compute done) ------------
    issueW(S1, 0);
    issueW(S1 + 1, 1);

    // ---------------- epilogue 1: h = relu(y1+b1) -> H tiles ----------------
    {
        const float* s_b1 = (const float*)(smem + BIAS1_OFF);
#pragma unroll
        for (int mi = 0; mi < 2; ++mi) {
            const int r0 = wrow * 32 + mi * 16 + g, r1 = r0 + 8;
#pragma unroll
            for (int ni = 0; ni < 4; ++ni) {
                const int col = wcol * 32 + ni * 8 + t4 * 2;
                const float ba = s_b1[col], bb = s_b1[col + 1];
                float v0 = fmaxf(acc[mi][ni][0] + ba, 0.f);
                float v1 = fmaxf(acc[mi][ni][1] + bb, 0.f);
                float v2 = fmaxf(acc[mi][ni][2] + ba, 0.f);
                float v3 = fmaxf(acc[mi][ni][3] + bb, 0.f);
                uint32_t h0 = pack2h(v0, v1);
                uint32_t h1 = pack2h(v2, v3);
                const int sub = col >> 6, kk = col & 63;
                const int bblk = kk >> 3, w2 = (kk & 7) * 2;
                char* tb = smem + sub * 8192;     // H subchunk -> XB(sub)
                char* d0 = tb + r0 * 128 + (((bblk ^ (r0 & 7))) << 4) + w2;
                char* d1 = tb + r1 * 128 + (((bblk ^ (r1 & 7))) << 4) + w2;
                *(uint32_t*)d0 = h0;
                *(uint32_t*)d1 = h1;
            }
        }
        // reset accumulators for GEMM2 (register reuse)
#pragma unroll
        for (int mi = 0; mi < 2; ++mi)
#pragma unroll
            for (int ni = 0; ni < 4; ++ni)
#pragma unroll
                for (int r = 0; r < 4; ++r) acc[mi][ni][r] = 0.f;
    }
    mbar_wait(sb + MBAR_OFF, (S1 / 2) & 1);
    mbar_wait(sb + MBAR_OFF + 8, (S1 / 2) & 1);
    __syncthreads();

    // ---------------- GEMM2: 2 subchunks (H in XB0/XB1, W2 in WB0/WB1) ------
    compute_sub(acc, sb + XB(0), sb + WB(0));
    compute_sub(acc, sb + XB(1), sb + WB(1));

    // ---------------- epilogue 2: LN -> m staged in smem -> coalesced out ---
    {
        const float* s_b2 = (const float*)(smem + BIAS2_OFF);
        float s[2][2] = {{0.f, 0.f}, {0.f, 0.f}};
        float ss[2][2] = {{0.f, 0.f}, {0.f, 0.f}};
#pragma unroll
        for (int mi = 0; mi < 2; ++mi)
#pragma unroll
            for (int ni = 0; ni < 4; ++ni) {
                const int col = wcol * 32 + ni * 8 + t4 * 2;
                const float ba = s_b2[col], bb = s_b2[col + 1];
                float y0 = acc[mi][ni][0] + ba, y1 = acc[mi][ni][1] + bb;
                float y2 = acc[mi][ni][2] + ba, y3 = acc[mi][ni][3] + bb;
                acc[mi][ni][0] = y0; acc[mi][ni][1] = y1;
                acc[mi][ni][2] = y2; acc[mi][ni][3] = y3;
                s[mi][0] += y0 + y1; ss[mi][0] += y0 * y0 + y1 * y1;
                s[mi][1] += y2 + y3; ss[mi][1] += y2 * y2 + y3 * y3;
            }
#pragma unroll
        for (int off = 1; off <= 2; off <<= 1)
#pragma unroll
            for (int mi = 0; mi < 2; ++mi)
#pragma unroll
                for (int h = 0; h < 2; ++h) {
                    s[mi][h] += __shfl_xor_sync(0xffffffffu, s[mi][h], off);
                    ss[mi][h] += __shfl_xor_sync(0xffffffffu, ss[mi][h], off);
                }
        float2* part = (float2*)(smem + PART_OFF);
        if (t4 == 0)
#pragma unroll
            for (int mi = 0; mi < 2; ++mi)
#pragma unroll
                for (int h = 0; h < 2; ++h) {
                    const int row = wrow * 32 + mi * 16 + g + h * 8;
                    part[row * 4 + wcol] = make_float2(s[mi][h], ss[mi][h]);
                }
        __syncthreads();

        // LN per owned row; stage m into smem m-tile (overwrites X/H + W bufs)
        const float* s_g = (const float*)(smem + GAM_OFF);
        const float* s_bb = (const float*)(smem + BET_OFF);
        float* mt = (float*)smem;                 // [64][MT_STRIDE] fp32
#pragma unroll
        for (int mi = 0; mi < 2; ++mi)
#pragma unroll
            for (int h = 0; h < 2; ++h) {
                const int row = wrow * 32 + mi * 16 + g + h * 8;
                float2 p0 = part[row * 4], p1 = part[row * 4 + 1];
                float2 p2 = part[row * 4 + 2], p3 = part[row * 4 + 3];
                const float mu = (p0.x + p1.x + p2.x + p3.x) * (1.f / 128.f);
                const float var =
                    (p0.y + p1.y + p2.y + p3.y) * (1.f / 128.f) - mu * mu;
                const float inv = rsqrtf(var + LN_EPS);
#pragma unroll
                for (int ni = 0; ni < 4; ++ni) {
                    const int col = wcol * 32 + ni * 8 + t4 * 2;
                    const float y0 = acc[mi][ni][h * 2];
                    const float y1 = acc[mi][ni][h * 2 + 1];
                    const float m0 = (y0 - mu) * inv * s_g[col] + s_bb[col];
                    const float m1 = (y1 - mu) * inv * s_g[col + 1] + s_bb[col + 1];
                    *(float2*)(mt + row * MT_STRIDE + col) = make_float2(m0, m1);
                }
            }
        __syncthreads();

        // coalesced output pass: 2048 float4 spans (64 rows x 32)
        const float* resb = EDGE ? ef : nf;
#pragma unroll
        for (int k = 0; k < 8; ++k) {
            const int i = k * 256 + tid;
            const int row = i >> 5, c4 = (i & 31) * 4;
            if (row < valid) {
                float4 m4 = *(const float4*)(mt + row * MT_STRIDE + c4);
                const size_t go = (size_t)(base + row) * 128 + c4;
                float4 r4 = *(const float4*)(resb + go);
                if (EDGE) {
                    const int rv = ((const int*)(smem + RIDX_OFF))[row];
                    float* ap = g_agg + (size_t)rv * 128 + c4;
                    red_add_v2(ap, m4.x, m4.y);
                    red_add_v2(ap + 2, m4.z, m4.w);
                }
                *(float4*)(out + go) =
                    make_float4(m4.x + r4.x, m4.y + r4.y, m4.z + r4.z, m4.w + r4.w);
            }
        }
    }
}

// ---------------------------------------------------------------------------
extern "C" void kernel_launch(void* const* d_in, const int* in_sizes, int n_in,
                              void* d_out, int out_size) {
    const float* nf  = (const float*)d_in[0];
    const float* ef  = (const float*)d_in[1];
    const int*   snd = (const int*)d_in[2];
    const int*   rcv = (const int*)d_in[3];
    const float* We1 = (const float*)d_in[4];
    const float* be1 = (const float*)d_in[5];
    const float* We2 = (const float*)d_in[6];
    const float* be2 = (const float*)d_in[7];
    const float* ge  = (const float*)d_in[8];
    const float* bbe = (const float*)d_in[9];
    const float* Wn1 = (const float*)d_in[10];
    const float* bn1 = (const float*)d_in[11];
    const float* Wn2 = (const float*)d_in[12];
    const float* bn2 = (const float*)d_in[13];
    const float* gn  = (const float*)d_in[14];
    const float* bbn = (const float*)d_in[15];

    float* out_nodes = (float*)d_out;
    float* out_edges = out_nodes + (size_t)N_NODES * 128;

    cudaFuncSetAttribute(gnb_kernel<6, true>,
                         cudaFuncAttributeMaxDynamicSharedMemorySize, SMEM_TOTAL);
    cudaFuncSetAttribute(gnb_kernel<4, false>,
                         cudaFuncAttributeMaxDynamicSharedMemorySize, SMEM_TOTAL);

    prep_w<<<448, 256>>>(We1, We2, Wn1, Wn2);
    conv_nf_kernel<<<6250, 256>>>(nf);       // 50000*32 float4s
    zero_agg_kernel<<<6250, 256>>>();

    gnb_kernel<6, true><<<N_EDGES / 64, 256, SMEM_TOTAL>>>(
        nf, ef, snd, rcv, be1, be2, ge, bbe, out_edges);

    gnb_kernel<4, false><<<(N_NODES + 63) / 64, 256, SMEM_TOTAL>>>(
        nf, nullptr, nullptr, nullptr, bn1, bn2, gn, bbn, out_nodes);
}